// round 16
// baseline (speedup 1.0000x reference)
#include <cuda_runtime.h>
#include <cuda_fp16.h>
#include <cstdint>

#define DIM 32
#define CIN 32
#define COUT 64
#define TILES_PER_B 248
#define NTILES (16 * TILES_PER_B)      // 3968
#define NBLOCKS 148

// ---- smem layout ----
#define SM_MBAR   0
#define SM_XS     1024                  // fp16 [cin][2][5][32] = 20480
#define SM_AT     22528                 // At[k=256][256B] = 65536
#define SM_B      88064                 // 27 * 4096 = 110592
#define SM_WSUM   198656                // 1024
#define SM_WACC   199680                // [16][64] float = 4096
#define SMEM_TOTAL 203776

__device__ __align__(256) __half g_wb[27 * 32 * 64];   // pre-swizzled fp16 taps
__device__ float g_part2[NBLOCKS * 16 * 64];

// ------------------------- helpers -------------------------
__device__ __forceinline__ uint32_t smem_u32(const void* p) {
    uint32_t a;
    asm("{ .reg .u64 t; cvta.to.shared.u64 t, %1; cvt.u32.u64 %0, t; }" : "=r"(a) : "l"(p));
    return a;
}
#define MBAR_INIT(addr, cnt) \
    asm volatile("mbarrier.init.shared.b64 [%0], %1;" :: "r"(addr), "r"(cnt) : "memory")
#define MBAR_EXPECT_TX(addr, bytes) \
    asm volatile("mbarrier.arrive.expect_tx.shared.b64 _, [%0], %1;" :: "r"(addr), "r"(bytes) : "memory")
#define MBAR_WAIT(addr, parity) do { \
    uint32_t _m = (addr); uint32_t _p = (parity); uint32_t _d; \
    asm volatile("{\n\t.reg .pred p;\n\t" \
        "mbarrier.try_wait.parity.acquire.cta.shared::cta.b64 p, [%1], %2;\n\t" \
        "selp.b32 %0, 1, 0, p;\n\t}" : "=r"(_d) : "r"(_m), "r"(_p) : "memory"); \
    if (!_d) { \
        asm volatile("{\n\t.reg .pred P1;\n\t" \
            "WL_%=:\n\t" \
            "mbarrier.try_wait.parity.acquire.cta.shared::cta.b64 P1, [%0], %1, 0x989680;\n\t" \
            "@P1 bra.uni WD_%=;\n\tbra.uni WL_%=;\n\tWD_%=:\n\t}" \
            :: "r"(_m), "r"(_p) : "memory"); \
    } } while (0)
#define FENCE_ASYNC() asm volatile("fence.proxy.async.shared::cta;" ::: "memory")
#define BULK_G2S(dst, src, bytes, mbar) \
    asm volatile("cp.async.bulk.shared::cta.global.mbarrier::complete_tx::bytes [%0], [%1], %2, [%3];" \
                 :: "r"(dst), "l"(src), "r"(bytes), "r"(mbar) : "memory")

__device__ __forceinline__ void ldsm_x4t(uint32_t (&r)[4], uint32_t a) {
    asm volatile("ldmatrix.sync.aligned.m8n8.x4.trans.shared.b16 {%0,%1,%2,%3}, [%4];"
                 : "=r"(r[0]), "=r"(r[1]), "=r"(r[2]), "=r"(r[3]) : "r"(a));
}
__device__ __forceinline__ void mma16816h(uint32_t (&d)[2], const uint32_t (&a)[4],
                                          uint32_t b0, uint32_t b1) {
    asm volatile("mma.sync.aligned.m16n8k16.row.col.f16.f16.f16.f16 "
                 "{%0,%1},{%2,%3,%4,%5},{%6,%7},{%0,%1};"
                 : "+r"(d[0]), "+r"(d[1])
                 : "r"(a[0]), "r"(a[1]), "r"(a[2]), "r"(a[3]), "r"(b0), "r"(b1));
}
__device__ __forceinline__ uint32_t hmax2u(uint32_t a, uint32_t b) {
    __half2 r = __hmax2(*(__half2*)&a, *(__half2*)&b);
    return *(uint32_t*)&r;
}

// half-slab prefetch: 5 float4 per thread (half = 0 -> j 0..4, half = 1 -> j 5..9)
__device__ __forceinline__ void ldg_half(const float* __restrict__ x,
                                         int b, int pd, int ph0, int tid, int half,
                                         float4 (&xr)[5]) {
    #pragma unroll
    for (int j = 0; j < 5; ++j) {
        int i = (half * 5 + j) * 256 + tid;
        int w4 = i & 7, r = i >> 3;
        int h = r % 5, r2 = r / 5;
        int dd = r2 & 1, cin = r2 >> 1;
        int hg = ph0 + h;
        float4 f = make_float4(0.f, 0.f, 0.f, 0.f);
        if (hg < 32)
            f = *(const float4*)(x + (size_t)((((b * CIN + cin) * DIM + (pd + dd)) * DIM + hg) * DIM) + w4 * 4);
        xr[j] = f;
    }
}
__device__ __forceinline__ void sts_half(char* sm, int tid, int half, const float4 (&xr)[5]) {
    #pragma unroll
    for (int j = 0; j < 5; ++j) {
        int i = (half * 5 + j) * 256 + tid;
        int w4 = i & 7, r = i >> 3;
        int h = r % 5, r2 = r / 5;
        int dd = r2 & 1, cin = r2 >> 1;
        __half2 p0 = __floats2half2_rn(xr[j].x, xr[j].y);
        __half2 p1 = __floats2half2_rn(xr[j].z, xr[j].w);
        *(uint2*)(sm + SM_XS + ((cin * 2 + dd) * 5 + h) * 64 + w4 * 8) =
            make_uint2(*(uint32_t*)&p0, *(uint32_t*)&p1);
    }
}

// one 16B At chunk: idx in [0,4096)
__device__ __forceinline__ void build_at_chunk(char* sm, int idx, int nh) {
    int q = idx & 15, krow = idx >> 4;
    int pos = krow >> 5, cin = krow & 31;
    int dd = pos >> 2, dh = (pos >> 1) & 1, dw = pos & 1;
    int phl = q >> 2, pw0 = (q & 3) * 8;
    const char* srow = sm + SM_XS + ((cin * 2 + dd) * 5 + (phl + dh)) * 64;
    uint4 v;
    if (dw == 0) {
        v = *(const uint4*)(srow + pw0 * 2);
    } else {
        uint4 a = *(const uint4*)(srow + pw0 * 2);
        uint32_t bb2 = *(const uint32_t*)(srow + pw0 * 2 + 16);
        v.x = __funnelshift_r(a.x, a.y, 16);
        v.y = __funnelshift_r(a.y, a.z, 16);
        v.z = __funnelshift_r(a.z, a.w, 16);
        v.w = __funnelshift_r(a.w, bb2, 16);
    }
    if (phl >= nh) v = make_uint4(0u, 0u, 0u, 0u);
    if (pw0 == 24) v.w &= 0x0000FFFFu;
    uint32_t off = (uint32_t)krow * 256u + (((uint32_t)q * 16u) ^ (((uint32_t)krow & 7u) << 4));
    *(uint4*)(sm + SM_AT + off) = v;
}

// ------------------- weight expansion (coalesced reads) ----
__global__ void init_wb(const float* __restrict__ w) {
    int idx = blockIdx.x * 256 + threadIdx.x;
    if (idx >= 27 * 32 * 64) return;
    float val = w[idx];
    int t    = idx % 27;
    int rem  = idx / 27;
    int cout = rem & 63;
    int cin  = rem >> 6;
    uint32_t off = (uint32_t)cin * 128u + (uint32_t)cout * 2u;
    uint32_t sw  = off ^ (((off >> 7) & 7) << 4);
    *(__half*)((char*)g_wb + (size_t)t * 4096 + sw) = __float2half(val);
}

// ------------------------------ main (persistent) ------------------------------
__global__ __launch_bounds__(256, 1)
void conv_mma_kernel(const float* __restrict__ x)
{
    extern __shared__ char sm[];
    const uint32_t smb = smem_u32(sm);
    const int tid = threadIdx.x, wid = tid >> 5, lid = tid & 31;
    const int bid = blockIdx.x;

    if (tid == 0) {
        MBAR_INIT(smb + SM_MBAR, 1);
        FENCE_ASYNC();
        MBAR_EXPECT_TX(smb + SM_MBAR, 110592u);
        BULK_G2S(smb + SM_B, (const char*)g_wb, 110592u, smb + SM_MBAR);
    }

    float* wacc = (float*)(sm + SM_WACC);
    for (int i = tid; i < 16 * 64; i += 256) wacc[i] = 0.f;
    float4 xr[5];
    {
        int b0 = bid / TILES_PER_B, r0 = bid % TILES_PER_B;
        int pd0 = r0 >> 3, ph00 = (r0 & 7) * 4;
        ldg_half(x, b0, pd0, ph00, tid, 0, xr);
        sts_half(sm, tid, 0, xr);
        ldg_half(x, b0, pd0, ph00, tid, 1, xr);
        sts_half(sm, tid, 1, xr);
    }
    __syncthreads();
    MBAR_WAIT(smb + SM_MBAR, 0);

    const int mt = wid >> 1, nt = wid & 1;
    const int m0 = mt * 32, n0 = nt * 32;
    const uint32_t xm = (uint32_t)(lid & 7) << 4;
    const int krA = ((lid >> 4) & 1) * 8 + (lid & 7);
    const int mc0 = m0 + ((lid >> 3) & 1) * 8;
    const uint32_t adrA0 = smb + SM_AT + krA * 256 + (((uint32_t)(mc0     ) * 2u) ^ xm);
    const uint32_t adrA1 = smb + SM_AT + krA * 256 + (((uint32_t)(mc0 + 16) * 2u) ^ xm);
    const int krB = ((lid >> 3) & 1) * 8 + (lid & 7);
    const int nc0 = n0 + ((lid >> 4) & 1) * 8;
    const uint32_t adrB0 = smb + SM_B + krB * 128 + (((uint32_t)(nc0     ) * 2u) ^ xm);
    const uint32_t adrB1 = smb + SM_B + krB * 128 + (((uint32_t)(nc0 + 16) * 2u) ^ xm);
    float* wsumf = (float*)(sm + SM_WSUM);

    for (int tile = bid; tile < NTILES; tile += NBLOCKS) {
        const int rr  = tile % TILES_PER_B;
        const int bb  = tile / TILES_PER_B;
        const int ph0 = (rr & 7) * 4;
        const int nh  = min(4, 31 - ph0);

        // ---- build At pos 0-3 only (cluster 0's inputs) ----
        for (int it = 0; it < 8; ++it)
            build_at_chunk(sm, it * 256 + tid, nh);

        const int nxt = tile + NBLOCKS;
        const bool hn = nxt < NTILES;
        const int nb = nxt / TILES_PER_B, nr = nxt % TILES_PER_B;
        const int npd = nr >> 3, nph0 = (nr & 7) * 4;
        if (hn) ldg_half(x, nb, npd, nph0, tid, 0, xr);   // half 0 in flight
        __syncthreads();             // (1) At pos0-3 visible; xs still live (pos4-7 pending)

        uint32_t vmax[2][4][2];
        #pragma unroll
        for (int i = 0; i < 2; ++i)
        #pragma unroll
        for (int j = 0; j < 4; ++j)
        #pragma unroll
        for (int k = 0; k < 2; ++k) vmax[i][j][k] = 0xFC00FC00u;

        #pragma unroll
        for (int cl = 0; cl < 2; ++cl) {
            // cluster 1 prologue: xs is fully free after sync (1b); stage next slab
            if (cl == 1 && hn) {
                sts_half(sm, tid, 0, xr);
                ldg_half(x, nb, npd, nph0, tid, 1, xr);
            }

            uint32_t acc[4][2][4][2];
            #pragma unroll
            for (int eo = 0; eo < 4; ++eo)
            #pragma unroll
            for (int i = 0; i < 2; ++i)
            #pragma unroll
            for (int j = 0; j < 4; ++j)
            #pragma unroll
            for (int k = 0; k < 2; ++k) acc[eo][i][j][k] = 0u;

            #pragma unroll
            for (int pos = 0; pos < 8; ++pos) {
                if (cl == 0 && (pos & 4)) continue;
                #pragma unroll
                for (int kb2 = 0; kb2 < 2; ++kb2) {
                    const int kb = pos * 2 + kb2;
                    uint32_t A0[4], A1[4];
                    ldsm_x4t(A0, adrA0 + kb * 4096);
                    ldsm_x4t(A1, adrA1 + kb * 4096);
                    #pragma unroll
                    for (int eo = 0; eo < 4; ++eo) {
                        const int e = cl * 4 + eo;
                        if (pos & ~e & 7) continue;
                        const int kd = (pos & 4) ? 0 : (((e >> 2) & 1) + 1);
                        const int kh = (pos & 2) ? 0 : (((e >> 1) & 1) + 1);
                        const int kw = (pos & 1) ? 0 : ((e & 1) + 1);
                        const int t  = (kd * 3 + kh) * 3 + kw;
                        uint32_t B0[4], B1[4];
                        ldsm_x4t(B0, adrB0 + t * 4096 + kb2 * 2048);
                        ldsm_x4t(B1, adrB1 + t * 4096 + kb2 * 2048);
                        mma16816h(acc[eo][0][0], A0, B0[0], B0[1]);
                        mma16816h(acc[eo][0][1], A0, B0[2], B0[3]);
                        mma16816h(acc[eo][0][2], A0, B1[0], B1[1]);
                        mma16816h(acc[eo][0][3], A0, B1[2], B1[3]);
                        mma16816h(acc[eo][1][0], A1, B0[0], B0[1]);
                        mma16816h(acc[eo][1][1], A1, B0[2], B0[3]);
                        mma16816h(acc[eo][1][2], A1, B1[0], B1[1]);
                        mma16816h(acc[eo][1][3], A1, B1[2], B1[3]);
                    }
                }
            }
            #pragma unroll
            for (int eo = 0; eo < 4; ++eo)
            #pragma unroll
            for (int i = 0; i < 2; ++i)
            #pragma unroll
            for (int j = 0; j < 4; ++j)
            #pragma unroll
            for (int k = 0; k < 2; ++k)
                vmax[i][j][k] = hmax2u(vmax[i][j][k], acc[eo][i][j][k]);

            // cluster 0 epilogue: build At pos 4-7 in cluster-0 MMA's issue shadow
            // (reads xs -- no next-tile xs writes have happened yet)
            if (cl == 0) {
                for (int it = 0; it < 8; ++it)
                    build_at_chunk(sm, 2048 + it * 256 + tid, nh);
                __syncthreads();     // (1b) At pos4-7 visible; xs now fully free
            }
        }

        // ---- epilogue ----
        #pragma unroll
        for (int nf = 0; nf < 4; ++nf) {
            __half2 a0 = *(__half2*)&vmax[0][nf][0];
            __half2 a1 = *(__half2*)&vmax[0][nf][1];
            __half2 b0 = *(__half2*)&vmax[1][nf][0];
            __half2 b1 = *(__half2*)&vmax[1][nf][1];
            float s0 = __low2float(a0) + __low2float(a1) + __low2float(b0) + __low2float(b1);
            float s1 = __high2float(a0) + __high2float(a1) + __high2float(b0) + __high2float(b1);
            #pragma unroll
            for (int off = 4; off < 32; off <<= 1) {
                s0 += __shfl_xor_sync(0xFFFFFFFFu, s0, off);
                s1 += __shfl_xor_sync(0xFFFFFFFFu, s1, off);
            }
            if (lid < 4) {
                wsumf[wid * 32 + nf * 8 + lid * 2]     = s0;
                wsumf[wid * 32 + nf * 8 + lid * 2 + 1] = s1;
            }
        }
        __syncthreads();             // (2) wsumf visible
        if (tid < 64) {
            int ntc = tid >> 5, cl2 = tid & 31;
            float s = wsumf[(0 * 2 + ntc) * 32 + cl2] + wsumf[(1 * 2 + ntc) * 32 + cl2]
                    + wsumf[(2 * 2 + ntc) * 32 + cl2] + wsumf[(3 * 2 + ntc) * 32 + cl2];
            wacc[bb * 64 + tid] += s;
        }
        if (hn) sts_half(sm, tid, 1, xr);   // overlaps wacc update
        __syncthreads();             // (3) xs + wacc settled
    }

    for (int i = tid; i < 16 * 64; i += 256)
        g_part2[bid * (16 * 64) + i] = wacc[i];
}

__global__ void finalize_kernel(const float* __restrict__ bias, float* __restrict__ out)
{
    const int bb = blockIdx.x;       // 16
    const int t  = threadIdx.x;      // 256
    const int c  = t >> 2, q = t & 3;
    float s = 0.f;
    #pragma unroll 8
    for (int i = q; i < NBLOCKS; i += 4)
        s += g_part2[i * (16 * 64) + bb * 64 + c];
    s += __shfl_down_sync(0xFFFFFFFFu, s, 2, 4);
    s += __shfl_down_sync(0xFFFFFFFFu, s, 1, 4);
    if (q == 0) {
        float v = 0.5f * (s * (1.0f / 29791.0f) + bias[c]);
        out[bb * 64 + c] = fminf(fmaxf(v, 0.f), 1.f);
    }
}

extern "C" void kernel_launch(void* const* d_in, const int* in_sizes, int n_in,
                              void* d_out, int out_size)
{
    const float* x    = (const float*)d_in[0];
    const float* w    = (const float*)d_in[1];
    const float* bias = (const float*)d_in[2];
    float* out = (float*)d_out;

    cudaFuncSetAttribute(conv_mma_kernel,
                         cudaFuncAttributeMaxDynamicSharedMemorySize, SMEM_TOTAL);

    init_wb<<<216, 256>>>(w);
    conv_mma_kernel<<<NBLOCKS, 256, SMEM_TOTAL>>>(x);
    finalize_kernel<<<16, 256>>>(bias, out);
}

// round 17
// speedup vs baseline: 1.0405x; 1.0405x over previous
#include <cuda_runtime.h>
#include <cuda_fp16.h>
#include <cstdint>

#define DIM 32
#define CIN 32
#define COUT 64
#define TILES_PER_B 248
#define NTILES (16 * TILES_PER_B)      // 3968
#define NBLOCKS 148

// ---- smem layout ----
#define SM_MBAR   0
#define SM_XS     1024                  // fp16 [cin][2][5][32] = 20480
#define SM_AT     22528                 // At[k=256][256B] = 65536
#define SM_B      88064                 // 27 * 4096 = 110592
#define SM_WSUM   198656                // 1024
#define SM_WACC   199680                // [16][64] float = 4096
#define SMEM_TOTAL 203776

__device__ __align__(256) __half g_wb[27 * 32 * 64];   // pre-swizzled fp16 taps
__device__ float g_part2[NBLOCKS * 16 * 64];

// ---- flattened schedule: entries 0..17 = cluster0, 18..53 = cluster1 ----
// order identical to R15's nested loops: pos outer, kb2, then eo  (bitwise-same accum order)
__device__ constexpr int TB_EO[54] = {
    0,1,2,3, 0,1,2,3, 1,3, 1,3, 2,3, 2,3, 3, 3,
    0,1,2,3, 0,1,2,3, 1,3, 1,3, 2,3, 2,3, 3, 3,
    0,1,2,3, 0,1,2,3, 1,3, 1,3, 2,3, 2,3, 3, 3
};
__device__ constexpr int TB_T[54] = {
    13,14,16,17, 13,14,16,17, 12,15, 12,15, 10,11, 10,11, 9, 9,
    22,23,25,26, 22,23,25,26, 21,24, 21,24, 19,20, 19,20, 18, 18,
     4, 5, 7, 8,  4, 5, 7, 8,  3, 6,  3, 6,  1, 2,  1, 2,  0, 0
};
__device__ constexpr int TB_KB2[54] = {
    0,0,0,0, 1,1,1,1, 0,0, 1,1, 0,0, 1,1, 0, 1,
    0,0,0,0, 1,1,1,1, 0,0, 1,1, 0,0, 1,1, 0, 1,
    0,0,0,0, 1,1,1,1, 0,0, 1,1, 0,0, 1,1, 0, 1
};
__device__ constexpr int TB_KB[54] = {
    0,0,0,0, 1,1,1,1, 2,2, 3,3, 4,4, 5,5, 6, 7,
    0,0,0,0, 1,1,1,1, 2,2, 3,3, 4,4, 5,5, 6, 7,
    8,8,8,8, 9,9,9,9, 10,10, 11,11, 12,12, 13,13, 14, 15
};

// ------------------------- helpers -------------------------
__device__ __forceinline__ uint32_t smem_u32(const void* p) {
    uint32_t a;
    asm("{ .reg .u64 t; cvta.to.shared.u64 t, %1; cvt.u32.u64 %0, t; }" : "=r"(a) : "l"(p));
    return a;
}
#define MBAR_INIT(addr, cnt) \
    asm volatile("mbarrier.init.shared.b64 [%0], %1;" :: "r"(addr), "r"(cnt) : "memory")
#define MBAR_EXPECT_TX(addr, bytes) \
    asm volatile("mbarrier.arrive.expect_tx.shared.b64 _, [%0], %1;" :: "r"(addr), "r"(bytes) : "memory")
#define MBAR_WAIT(addr, parity) do { \
    uint32_t _m = (addr); uint32_t _p = (parity); uint32_t _d; \
    asm volatile("{\n\t.reg .pred p;\n\t" \
        "mbarrier.try_wait.parity.acquire.cta.shared::cta.b64 p, [%1], %2;\n\t" \
        "selp.b32 %0, 1, 0, p;\n\t}" : "=r"(_d) : "r"(_m), "r"(_p) : "memory"); \
    if (!_d) { \
        asm volatile("{\n\t.reg .pred P1;\n\t" \
            "WL_%=:\n\t" \
            "mbarrier.try_wait.parity.acquire.cta.shared::cta.b64 P1, [%0], %1, 0x989680;\n\t" \
            "@P1 bra.uni WD_%=;\n\tbra.uni WL_%=;\n\tWD_%=:\n\t}" \
            :: "r"(_m), "r"(_p) : "memory"); \
    } } while (0)
#define FENCE_ASYNC() asm volatile("fence.proxy.async.shared::cta;" ::: "memory")
#define BULK_G2S(dst, src, bytes, mbar) \
    asm volatile("cp.async.bulk.shared::cta.global.mbarrier::complete_tx::bytes [%0], [%1], %2, [%3];" \
                 :: "r"(dst), "l"(src), "r"(bytes), "r"(mbar) : "memory")

__device__ __forceinline__ void ldsm_x4t(uint32_t* r, uint32_t a) {
    asm volatile("ldmatrix.sync.aligned.m8n8.x4.trans.shared.b16 {%0,%1,%2,%3}, [%4];"
                 : "=r"(r[0]), "=r"(r[1]), "=r"(r[2]), "=r"(r[3]) : "r"(a));
}
__device__ __forceinline__ void mma16816h(uint32_t (&d)[2], const uint32_t* a,
                                          uint32_t b0, uint32_t b1) {
    asm volatile("mma.sync.aligned.m16n8k16.row.col.f16.f16.f16.f16 "
                 "{%0,%1},{%2,%3,%4,%5},{%6,%7},{%0,%1};"
                 : "+r"(d[0]), "+r"(d[1])
                 : "r"(a[0]), "r"(a[1]), "r"(a[2]), "r"(a[3]), "r"(b0), "r"(b1));
}
__device__ __forceinline__ uint32_t hmax2u(uint32_t a, uint32_t b) {
    __half2 r = __hmax2(*(__half2*)&a, *(__half2*)&b);
    return *(uint32_t*)&r;
}

// half-slab prefetch: 5 float4 per thread (half = 0 -> j 0..4, half = 1 -> j 5..9)
__device__ __forceinline__ void ldg_half(const float* __restrict__ x,
                                         int b, int pd, int ph0, int tid, int half,
                                         float4 (&xr)[5]) {
    #pragma unroll
    for (int j = 0; j < 5; ++j) {
        int i = (half * 5 + j) * 256 + tid;
        int w4 = i & 7, r = i >> 3;
        int h = r % 5, r2 = r / 5;
        int dd = r2 & 1, cin = r2 >> 1;
        int hg = ph0 + h;
        float4 f = make_float4(0.f, 0.f, 0.f, 0.f);
        if (hg < 32)
            f = *(const float4*)(x + (size_t)((((b * CIN + cin) * DIM + (pd + dd)) * DIM + hg) * DIM) + w4 * 4);
        xr[j] = f;
    }
}
__device__ __forceinline__ void sts_half(char* sm, int tid, int half, const float4 (&xr)[5]) {
    #pragma unroll
    for (int j = 0; j < 5; ++j) {
        int i = (half * 5 + j) * 256 + tid;
        int w4 = i & 7, r = i >> 3;
        int h = r % 5, r2 = r / 5;
        int dd = r2 & 1, cin = r2 >> 1;
        __half2 p0 = __floats2half2_rn(xr[j].x, xr[j].y);
        __half2 p1 = __floats2half2_rn(xr[j].z, xr[j].w);
        *(uint2*)(sm + SM_XS + ((cin * 2 + dd) * 5 + h) * 64 + w4 * 8) =
            make_uint2(*(uint32_t*)&p0, *(uint32_t*)&p1);
    }
}

// one 16B At chunk: idx in [0,4096)
__device__ __forceinline__ void build_at_chunk(char* sm, int idx, int nh) {
    int q = idx & 15, krow = idx >> 4;
    int pos = krow >> 5, cin = krow & 31;
    int dd = pos >> 2, dh = (pos >> 1) & 1, dw = pos & 1;
    int phl = q >> 2, pw0 = (q & 3) * 8;
    const char* srow = sm + SM_XS + ((cin * 2 + dd) * 5 + (phl + dh)) * 64;
    uint4 v;
    if (dw == 0) {
        v = *(const uint4*)(srow + pw0 * 2);
    } else {
        uint4 a = *(const uint4*)(srow + pw0 * 2);
        uint32_t bb2 = *(const uint32_t*)(srow + pw0 * 2 + 16);
        v.x = __funnelshift_r(a.x, a.y, 16);
        v.y = __funnelshift_r(a.y, a.z, 16);
        v.z = __funnelshift_r(a.z, a.w, 16);
        v.w = __funnelshift_r(a.w, bb2, 16);
    }
    if (phl >= nh) v = make_uint4(0u, 0u, 0u, 0u);
    if (pw0 == 24) v.w &= 0x0000FFFFu;
    uint32_t off = (uint32_t)krow * 256u + (((uint32_t)q * 16u) ^ (((uint32_t)krow & 7u) << 4));
    *(uint4*)(sm + SM_AT + off) = v;
}

// ------------------- weight expansion (coalesced reads) ----
__global__ void init_wb(const float* __restrict__ w) {
    int idx = blockIdx.x * 256 + threadIdx.x;
    if (idx >= 27 * 32 * 64) return;
    float val = w[idx];
    int t    = idx % 27;
    int rem  = idx / 27;
    int cout = rem & 63;
    int cin  = rem >> 6;
    uint32_t off = (uint32_t)cin * 128u + (uint32_t)cout * 2u;
    uint32_t sw  = off ^ (((off >> 7) & 7) << 4);
    *(__half*)((char*)g_wb + (size_t)t * 4096 + sw) = __float2half(val);
}

// ------------------------------ main (persistent) ------------------------------
__global__ __launch_bounds__(256, 1)
void conv_mma_kernel(const float* __restrict__ x)
{
    extern __shared__ char sm[];
    const uint32_t smb = smem_u32(sm);
    const int tid = threadIdx.x, wid = tid >> 5, lid = tid & 31;
    const int bid = blockIdx.x;

    if (tid == 0) {
        MBAR_INIT(smb + SM_MBAR, 1);
        FENCE_ASYNC();
        MBAR_EXPECT_TX(smb + SM_MBAR, 110592u);
        BULK_G2S(smb + SM_B, (const char*)g_wb, 110592u, smb + SM_MBAR);
    }

    float* wacc = (float*)(sm + SM_WACC);
    for (int i = tid; i < 16 * 64; i += 256) wacc[i] = 0.f;
    float4 xr[5];
    {
        int b0 = bid / TILES_PER_B, r0 = bid % TILES_PER_B;
        int pd0 = r0 >> 3, ph00 = (r0 & 7) * 4;
        ldg_half(x, b0, pd0, ph00, tid, 0, xr);
        sts_half(sm, tid, 0, xr);
        ldg_half(x, b0, pd0, ph00, tid, 1, xr);
        sts_half(sm, tid, 1, xr);
    }
    __syncthreads();
    MBAR_WAIT(smb + SM_MBAR, 0);

    const int mt = wid >> 1, nt = wid & 1;
    const int m0 = mt * 32, n0 = nt * 32;
    const uint32_t xm = (uint32_t)(lid & 7) << 4;
    const int krA = ((lid >> 4) & 1) * 8 + (lid & 7);
    const int mc0 = m0 + ((lid >> 3) & 1) * 8;
    const uint32_t adrA0 = smb + SM_AT + krA * 256 + (((uint32_t)(mc0     ) * 2u) ^ xm);
    const uint32_t adrA1 = smb + SM_AT + krA * 256 + (((uint32_t)(mc0 + 16) * 2u) ^ xm);
    const int krB = ((lid >> 3) & 1) * 8 + (lid & 7);
    const int nc0 = n0 + ((lid >> 4) & 1) * 8;
    const uint32_t adrB0 = smb + SM_B + krB * 128 + (((uint32_t)(nc0     ) * 2u) ^ xm);
    const uint32_t adrB1 = smb + SM_B + krB * 128 + (((uint32_t)(nc0 + 16) * 2u) ^ xm);
    float* wsumf = (float*)(sm + SM_WSUM);

    for (int tile = bid; tile < NTILES; tile += NBLOCKS) {
        const int rr  = tile % TILES_PER_B;
        const int bb  = tile / TILES_PER_B;
        const int ph0 = (rr & 7) * 4;
        const int nh  = min(4, 31 - ph0);

        // ---- build full At (pos 0-7) ----
        for (int it = 0; it < 16; ++it)
            build_at_chunk(sm, it * 256 + tid, nh);

        const int nxt = tile + NBLOCKS;
        const bool hn = nxt < NTILES;
        const int nb = nxt / TILES_PER_B, nr = nxt % TILES_PER_B;
        const int npd = nr >> 3, nph0 = (nr & 7) * 4;
        if (hn) ldg_half(x, nb, npd, nph0, tid, 0, xr);   // half 0 in flight
        __syncthreads();             // (1) At visible; xs free

        // ---- pipelined MMA over flat 54-entry schedule ----
        uint32_t vmax[2][4][2];
        #pragma unroll
        for (int i = 0; i < 2; ++i)
        #pragma unroll
        for (int j = 0; j < 4; ++j)
        #pragma unroll
        for (int k = 0; k < 2; ++k) vmax[i][j][k] = 0xFC00FC00u;

        uint32_t acc[4][2][4][2];
        #pragma unroll
        for (int eo = 0; eo < 4; ++eo)
        #pragma unroll
        for (int i = 0; i < 2; ++i)
        #pragma unroll
        for (int j = 0; j < 4; ++j)
        #pragma unroll
        for (int k = 0; k < 2; ++k) acc[eo][i][j][k] = 0u;

        uint32_t Abuf[2][8], Bbuf[2][8];
        ldsm_x4t(&Abuf[0][0], adrA0 + TB_KB[0] * 4096);
        ldsm_x4t(&Abuf[0][4], adrA1 + TB_KB[0] * 4096);
        ldsm_x4t(&Bbuf[0][0], adrB0 + TB_T[0] * 4096 + TB_KB2[0] * 2048);
        ldsm_x4t(&Bbuf[0][4], adrB1 + TB_T[0] * 4096 + TB_KB2[0] * 2048);

        int ab = 0;
        #pragma unroll
        for (int i = 0; i < 54; ++i) {
            const int cb = i & 1, nb2 = cb ^ 1;
            const bool newA = (i + 1 < 54) && (TB_KB[i + 1] != TB_KB[i]);
            if (i + 1 < 54) {
                if (newA) {
                    ldsm_x4t(&Abuf[ab ^ 1][0], adrA0 + TB_KB[i + 1] * 4096);
                    ldsm_x4t(&Abuf[ab ^ 1][4], adrA1 + TB_KB[i + 1] * 4096);
                }
                ldsm_x4t(&Bbuf[nb2][0], adrB0 + TB_T[i + 1] * 4096 + TB_KB2[i + 1] * 2048);
                ldsm_x4t(&Bbuf[nb2][4], adrB1 + TB_T[i + 1] * 4096 + TB_KB2[i + 1] * 2048);
            }
            const int eo = TB_EO[i];
            mma16816h(acc[eo][0][0], &Abuf[ab][0], Bbuf[cb][0], Bbuf[cb][1]);
            mma16816h(acc[eo][0][1], &Abuf[ab][0], Bbuf[cb][2], Bbuf[cb][3]);
            mma16816h(acc[eo][0][2], &Abuf[ab][0], Bbuf[cb][4], Bbuf[cb][5]);
            mma16816h(acc[eo][0][3], &Abuf[ab][0], Bbuf[cb][6], Bbuf[cb][7]);
            mma16816h(acc[eo][1][0], &Abuf[ab][4], Bbuf[cb][0], Bbuf[cb][1]);
            mma16816h(acc[eo][1][1], &Abuf[ab][4], Bbuf[cb][2], Bbuf[cb][3]);
            mma16816h(acc[eo][1][2], &Abuf[ab][4], Bbuf[cb][4], Bbuf[cb][5]);
            mma16816h(acc[eo][1][3], &Abuf[ab][4], Bbuf[cb][6], Bbuf[cb][7]);
            if (newA) ab ^= 1;
            if (i == 17 || i == 53) {      // cluster boundary: fold + reset
                #pragma unroll
                for (int e2 = 0; e2 < 4; ++e2)
                #pragma unroll
                for (int a2 = 0; a2 < 2; ++a2)
                #pragma unroll
                for (int j = 0; j < 4; ++j)
                #pragma unroll
                for (int k = 0; k < 2; ++k) {
                    vmax[a2][j][k] = hmax2u(vmax[a2][j][k], acc[e2][a2][j][k]);
                    acc[e2][a2][j][k] = 0u;
                }
                if (i == 17 && hn) {      // cluster-1 prologue: stage next slab
                    sts_half(sm, tid, 0, xr);
                    ldg_half(x, nb, npd, nph0, tid, 1, xr);
                }
            }
        }

        // ---- epilogue ----
        #pragma unroll
        for (int nf = 0; nf < 4; ++nf) {
            __half2 a0 = *(__half2*)&vmax[0][nf][0];
            __half2 a1 = *(__half2*)&vmax[0][nf][1];
            __half2 b0 = *(__half2*)&vmax[1][nf][0];
            __half2 b1 = *(__half2*)&vmax[1][nf][1];
            float s0 = __low2float(a0) + __low2float(a1) + __low2float(b0) + __low2float(b1);
            float s1 = __high2float(a0) + __high2float(a1) + __high2float(b0) + __high2float(b1);
            #pragma unroll
            for (int off = 4; off < 32; off <<= 1) {
                s0 += __shfl_xor_sync(0xFFFFFFFFu, s0, off);
                s1 += __shfl_xor_sync(0xFFFFFFFFu, s1, off);
            }
            if (lid < 4) {
                wsumf[wid * 32 + nf * 8 + lid * 2]     = s0;
                wsumf[wid * 32 + nf * 8 + lid * 2 + 1] = s1;
            }
        }
        __syncthreads();             // (2) wsumf visible
        if (tid < 64) {
            int ntc = tid >> 5, cl2 = tid & 31;
            float s = wsumf[(0 * 2 + ntc) * 32 + cl2] + wsumf[(1 * 2 + ntc) * 32 + cl2]
                    + wsumf[(2 * 2 + ntc) * 32 + cl2] + wsumf[(3 * 2 + ntc) * 32 + cl2];
            wacc[bb * 64 + tid] += s;
        }
        if (hn) sts_half(sm, tid, 1, xr);   // overlaps wacc update
        __syncthreads();             // (3) xs + wacc settled
    }

    for (int i = tid; i < 16 * 64; i += 256)
        g_part2[bid * (16 * 64) + i] = wacc[i];
}

__global__ void finalize_kernel(const float* __restrict__ bias, float* __restrict__ out)
{
    const int bb = blockIdx.x;       // 16
    const int t  = threadIdx.x;      // 256
    const int c  = t >> 2, q = t & 3;
    float s = 0.f;
    #pragma unroll 8
    for (int i = q; i < NBLOCKS; i += 4)
        s += g_part2[i * (16 * 64) + bb * 64 + c];
    s += __shfl_down_sync(0xFFFFFFFFu, s, 2, 4);
    s += __shfl_down_sync(0xFFFFFFFFu, s, 1, 4);
    if (q == 0) {
        float v = 0.5f * (s * (1.0f / 29791.0f) + bias[c]);
        out[bb * 64 + c] = fminf(fmaxf(v, 0.f), 1.f);
    }
}

extern "C" void kernel_launch(void* const* d_in, const int* in_sizes, int n_in,
                              void* d_out, int out_size)
{
    const float* x    = (const float*)d_in[0];
    const float* w    = (const float*)d_in[1];
    const float* bias = (const float*)d_in[2];
    float* out = (float*)d_out;

    cudaFuncSetAttribute(conv_mma_kernel,
                         cudaFuncAttributeMaxDynamicSharedMemorySize, SMEM_TOTAL);

    init_wb<<<216, 256>>>(w);
    conv_mma_kernel<<<NBLOCKS, 256, SMEM_TOTAL>>>(x);
    finalize_kernel<<<16, 256>>>(bias, out);
}